// round 1
// baseline (speedup 1.0000x reference)
#include <cuda_runtime.h>

#define N_NODES 50000
#define N_EDGES 640000
#define D 128
#define N_RELS 16
#define N_NT 8
#define TILE 128

#define EG (N_EDGES / TILE + N_RELS)            /* 5016 grid blocks for edge gemm */
#define NG ((N_NODES + TILE - 1) / TILE + N_NT) /* 399 grid blocks for node gemm */
#define E_PAD (EG * TILE)
#define N_PAD (NG * TILE)

/* dynamic smem: sW = 64*128*8 = 65536 ; sA = 128*65*8 = 66560, staging 128*132*4 = 67584 (overlaps sA) */
#define SMEM_BYTES (65536 + 67584)

/* ------------------------------ scratch ------------------------------ */
__device__ int   g_counts[N_NODES * N_RELS]; /* per (dst,rel) in-degree */
__device__ int   g_rel_cnt[N_RELS];
__device__ int   g_rel_cur[N_RELS];
__device__ int   g_nt_cnt[N_NT];
__device__ int   g_nt_cur[N_NT];
__device__ int   g_eperm[E_PAD];             /* edge ids sorted by rel, padded (-1) */
__device__ int   g_nperm[N_PAD];             /* node ids sorted by ntype, padded (-1) */
__device__ float g_agg[N_NODES * D];
__device__ int   g_ntiles[2];

/* ------------------------------ helpers ------------------------------ */
__device__ __forceinline__ void fma2(unsigned long long& d, unsigned long long a,
                                     unsigned long long b) {
    asm("fma.rn.f32x2 %0, %1, %2, %0;" : "+l"(d) : "l"(a), "l"(b));
}
__device__ __forceinline__ unsigned long long pack2(float x, float y) {
    float2 f = make_float2(x, y);
    return *reinterpret_cast<unsigned long long*>(&f);
}
__device__ __forceinline__ float2 unpack2(unsigned long long v) {
    return *reinterpret_cast<float2*>(&v);
}

/* ------------------------------ setup kernels ------------------------------ */
__global__ void k_zero() {
    int i = blockIdx.x * blockDim.x + threadIdx.x;
    int stride = gridDim.x * blockDim.x;
    for (int j = i; j < N_NODES * D; j += stride) g_agg[j] = 0.0f;
    for (int j = i; j < N_NODES * N_RELS; j += stride) g_counts[j] = 0;
    for (int j = i; j < E_PAD; j += stride) g_eperm[j] = -1;
    for (int j = i; j < N_PAD; j += stride) g_nperm[j] = -1;
    if (i < N_RELS) g_rel_cnt[i] = 0;
    if (i < N_NT) g_nt_cnt[i] = 0;
}

__global__ void k_hist(const int* __restrict__ dst, const int* __restrict__ etypes,
                       const int* __restrict__ ntypes) {
    __shared__ int sh[N_RELS + N_NT];
    int tid = threadIdx.x;
    if (tid < N_RELS + N_NT) sh[tid] = 0;
    __syncthreads();
    int i = blockIdx.x * blockDim.x + tid;
    int stride = gridDim.x * blockDim.x;
    for (int e = i; e < N_EDGES; e += stride) {
        int t = etypes[e];
        atomicAdd(&sh[t], 1);
        atomicAdd(&g_counts[dst[e] * N_RELS + t], 1);
    }
    for (int n = i; n < N_NODES; n += stride) atomicAdd(&sh[N_RELS + ntypes[n]], 1);
    __syncthreads();
    if (tid < N_RELS) atomicAdd(&g_rel_cnt[tid], sh[tid]);
    else if (tid < N_RELS + N_NT) atomicAdd(&g_nt_cnt[tid - N_RELS], sh[tid]);
}

__global__ void k_scan() {
    int off = 0;
    for (int t = 0; t < N_RELS; t++) {
        g_rel_cur[t] = off;
        off += ((g_rel_cnt[t] + TILE - 1) / TILE) * TILE;
    }
    g_ntiles[0] = off / TILE;
    off = 0;
    for (int t = 0; t < N_NT; t++) {
        g_nt_cur[t] = off;
        off += ((g_nt_cnt[t] + TILE - 1) / TILE) * TILE;
    }
    g_ntiles[1] = off / TILE;
}

__global__ void k_scatter(const int* __restrict__ etypes, const int* __restrict__ ntypes) {
    __shared__ int s_cnt[N_RELS], s_base[N_RELS];
    const int CH = 4096;
    int tid = threadIdx.x;

    int nch = (N_EDGES + CH - 1) / CH;
    for (int ch = blockIdx.x; ch < nch; ch += gridDim.x) {
        int lo = ch * CH, hi = min(lo + CH, N_EDGES);
        if (tid < N_RELS) s_cnt[tid] = 0;
        __syncthreads();
        for (int e = lo + tid; e < hi; e += blockDim.x) atomicAdd(&s_cnt[etypes[e]], 1);
        __syncthreads();
        if (tid < N_RELS) {
            s_base[tid] = atomicAdd(&g_rel_cur[tid], s_cnt[tid]);
            s_cnt[tid] = 0;
        }
        __syncthreads();
        for (int e = lo + tid; e < hi; e += blockDim.x) {
            int t = etypes[e];
            g_eperm[s_base[t] + atomicAdd(&s_cnt[t], 1)] = e;
        }
        __syncthreads();
    }

    nch = (N_NODES + CH - 1) / CH;
    for (int ch = blockIdx.x; ch < nch; ch += gridDim.x) {
        int lo = ch * CH, hi = min(lo + CH, N_NODES);
        if (tid < N_NT) s_cnt[tid] = 0;
        __syncthreads();
        for (int n = lo + tid; n < hi; n += blockDim.x) atomicAdd(&s_cnt[ntypes[n]], 1);
        __syncthreads();
        if (tid < N_NT) {
            s_base[tid] = atomicAdd(&g_nt_cur[tid], s_cnt[tid]);
            s_cnt[tid] = 0;
        }
        __syncthreads();
        for (int n = lo + tid; n < hi; n += blockDim.x) {
            int t = ntypes[n];
            g_nperm[s_base[t] + atomicAdd(&s_cnt[t], 1)] = n;
        }
        __syncthreads();
    }
}

/* ------------------------------ edge GEMM + scatter-add ------------------------------ */
/* One block = 128 edges of a single relation. 256 threads, 8x8 thread tile, f32x2 packed
 * FMA. Epilogue: (dot + b_edge[rel]) / count(dst,rel), staged in smem, red.v4 into g_agg. */
__global__ __launch_bounds__(256, 1) void k_edge(
    const float* __restrict__ feats, const float* __restrict__ W_edge,
    const float* __restrict__ b_edge, const int* __restrict__ src,
    const int* __restrict__ dst, const int* __restrict__ etypes) {
    if ((int)blockIdx.x >= g_ntiles[0]) return;

    extern __shared__ char smem[];
    unsigned long long* sW = (unsigned long long*)smem;              /* [64][128] k-pair packed */
    unsigned long long* sA = (unsigned long long*)(smem + 65536);    /* [128][65] k-pair packed */
    float* sOut = (float*)(smem + 65536);                            /* [128][132] staging */
    __shared__ int sDst[TILE];
    __shared__ int sSrc[TILE];
    __shared__ float sInv[TILE];
    __shared__ int sRel;

    const int tid = threadIdx.x;
    const int base = blockIdx.x * TILE;

    if (tid < TILE) {
        int e = g_eperm[base + tid];
        int d_ = -1, s_ = 0;
        float inv = 0.0f;
        if (e >= 0) {
            d_ = dst[e];
            s_ = src[e];
            int t = etypes[e];
            inv = 1.0f / (float)g_counts[d_ * N_RELS + t];
            if (tid == 0) sRel = t; /* row 0 of a live tile is always valid */
        }
        sDst[tid] = d_;
        sSrc[tid] = s_;
        sInv[tid] = inv;
    }
    __syncthreads();
    const int rel = sRel;

    /* gather feats rows: 2 threads per row, float4 loads, pack consecutive k into ull */
    {
        int r = tid >> 1, half = tid & 1;
        bool valid = sDst[r] >= 0;
        const float4* fp = (const float4*)(feats + (size_t)sSrc[r] * D) + half * 16;
#pragma unroll
        for (int i = 0; i < 16; i++) {
            float4 v = valid ? fp[i] : make_float4(0.f, 0.f, 0.f, 0.f);
            sA[r * 65 + half * 32 + i * 2] = pack2(v.x, v.y);
            sA[r * 65 + half * 32 + i * 2 + 1] = pack2(v.z, v.w);
        }
    }

    /* load W_edge[rel], packing k-pairs: sW[kk][c] = {W[2kk][c], W[2kk+1][c]} */
    {
        const float* Wr = W_edge + (size_t)rel * D * D;
#pragma unroll
        for (int i = 0; i < 8; i++) {
            int idx = tid + 256 * i;   /* 0..2047 */
            int kk = idx >> 5, cg = idx & 31;
            float4 lo = *(const float4*)(Wr + (2 * kk) * D + cg * 4);
            float4 hi = *(const float4*)(Wr + (2 * kk + 1) * D + cg * 4);
            sW[kk * 128 + cg * 4 + 0] = pack2(lo.x, hi.x);
            sW[kk * 128 + cg * 4 + 1] = pack2(lo.y, hi.y);
            sW[kk * 128 + cg * 4 + 2] = pack2(lo.z, hi.z);
            sW[kk * 128 + cg * 4 + 3] = pack2(lo.w, hi.w);
        }
    }
    __syncthreads();

    const int ty = tid >> 4, tx = tid & 15;
    unsigned long long acc[8][8];
#pragma unroll
    for (int i = 0; i < 8; i++)
#pragma unroll
        for (int j = 0; j < 8; j++) acc[i][j] = 0ull;

#pragma unroll 4
    for (int kk = 0; kk < D / 2; kk++) {
        unsigned long long a[8], b[8];
#pragma unroll
        for (int i = 0; i < 8; i++) a[i] = sA[(ty * 8 + i) * 65 + kk];
#pragma unroll
        for (int j = 0; j < 8; j++) b[j] = sW[kk * 128 + tx + 16 * j];
#pragma unroll
        for (int i = 0; i < 8; i++)
#pragma unroll
            for (int j = 0; j < 8; j++) fma2(acc[i][j], a[i], b[j]);
    }

    float bc[8];
#pragma unroll
    for (int j = 0; j < 8; j++) bc[j] = b_edge[rel * D + tx + 16 * j];

    __syncthreads(); /* everyone done reading sA before staging overwrite */
#pragma unroll
    for (int i = 0; i < 8; i++) {
        int r = ty * 8 + i;
        float inv = sInv[r];
#pragma unroll
        for (int j = 0; j < 8; j++) {
            float2 f = unpack2(acc[i][j]);
            sOut[r * 132 + tx + 16 * j] = (f.x + f.y + bc[j]) * inv;
        }
    }
    __syncthreads();

    /* scatter-add: 2 threads per row, vector red into L2-resident agg */
    {
        int r = tid >> 1, half = tid & 1;
        int d_ = sDst[r];
        if (d_ >= 0) {
            float* gp = g_agg + (size_t)d_ * D + half * 64;
            const float* sp = sOut + r * 132 + half * 64;
#pragma unroll
            for (int m = 0; m < 16; m++) {
                float4 v = *(const float4*)(sp + 4 * m);
                asm volatile("red.global.add.v4.f32 [%0], {%1,%2,%3,%4};"
                             :: "l"(gp + 4 * m), "f"(v.x), "f"(v.y), "f"(v.z), "f"(v.w)
                             : "memory");
            }
        }
    }
}

/* ------------------------------ node GEMM + residual + relu ------------------------------ */
__global__ __launch_bounds__(256, 1) void k_node(
    const float* __restrict__ feats, const float* __restrict__ W_node,
    const float* __restrict__ b_node, float* __restrict__ out) {
    if ((int)blockIdx.x >= g_ntiles[1]) return;

    extern __shared__ char smem[];
    unsigned long long* sW = (unsigned long long*)smem;
    unsigned long long* sA = (unsigned long long*)(smem + 65536);
    float* sOut = (float*)(smem + 65536);
    __shared__ int sNode[TILE];
    __shared__ int sNt;

    const int tid = threadIdx.x;
    const int base = blockIdx.x * TILE;

    if (tid < TILE) {
        int n = g_nperm[base + tid];
        sNode[tid] = n;
        if (tid == 0) sNt = (n >= 0) ? 0 : 0; /* placeholder; set below */
    }
    __syncthreads();
    if (tid == 0) {
        /* row 0 of a live tile is always a valid node; recover its type from bin layout:
           find type by comparing against cumulative bins is avoidable — just reload. */
    }
    /* fetch ntype of first (always-valid) row directly */
    __shared__ int sT;
    if (tid == 0) {
        /* all rows in this tile share the node type by construction */
        sT = -1;
    }
    __syncthreads();
    /* ntype lookup: we don't have ntypes here; pass via feats? -> simpler: recompute below */
    /* NOTE: ntypes pointer passed through W-load path; see launch (extra param). */
    (void)sNt;

    /* The real implementation passes ntypes; this stub never executes. */
    (void)sW; (void)sA; (void)sOut; (void)sNode; (void)sT;
    (void)feats; (void)W_node; (void)b_node; (void)out; (void)base;
}

/* full node kernel (with ntypes) */
__global__ __launch_bounds__(256, 1) void k_node2(
    const float* __restrict__ feats, const float* __restrict__ W_node,
    const float* __restrict__ b_node, const int* __restrict__ ntypes,
    float* __restrict__ out) {
    if ((int)blockIdx.x >= g_ntiles[1]) return;

    extern __shared__ char smem[];
    unsigned long long* sW = (unsigned long long*)smem;
    unsigned long long* sA = (unsigned long long*)(smem + 65536);
    float* sOut = (float*)(smem + 65536);
    __shared__ int sNode[TILE];
    __shared__ int sT;

    const int tid = threadIdx.x;
    const int base = blockIdx.x * TILE;

    if (tid < TILE) {
        int n = g_nperm[base + tid];
        sNode[tid] = n;
        if (tid == 0) sT = ntypes[n]; /* row 0 always valid in a live tile */
    }
    __syncthreads();
    const int nt = sT;

    {
        int r = tid >> 1, half = tid & 1;
        int n = sNode[r];
        bool valid = n >= 0;
        const float4* fp = (const float4*)(feats + (size_t)(valid ? n : 0) * D) + half * 16;
#pragma unroll
        for (int i = 0; i < 16; i++) {
            float4 v = valid ? fp[i] : make_float4(0.f, 0.f, 0.f, 0.f);
            sA[r * 65 + half * 32 + i * 2] = pack2(v.x, v.y);
            sA[r * 65 + half * 32 + i * 2 + 1] = pack2(v.z, v.w);
        }
    }
    {
        const float* Wr = W_node + (size_t)nt * D * D;
#pragma unroll
        for (int i = 0; i < 8; i++) {
            int idx = tid + 256 * i;
            int kk = idx >> 5, cg = idx & 31;
            float4 lo = *(const float4*)(Wr + (2 * kk) * D + cg * 4);
            float4 hi = *(const float4*)(Wr + (2 * kk + 1) * D + cg * 4);
            sW[kk * 128 + cg * 4 + 0] = pack2(lo.x, hi.x);
            sW[kk * 128 + cg * 4 + 1] = pack2(lo.y, hi.y);
            sW[kk * 128 + cg * 4 + 2] = pack2(lo.z, hi.z);
            sW[kk * 128 + cg * 4 + 3] = pack2(lo.w, hi.w);
        }
    }
    __syncthreads();

    const int ty = tid >> 4, tx = tid & 15;
    unsigned long long acc[8][8];
#pragma unroll
    for (int i = 0; i < 8; i++)
#pragma unroll
        for (int j = 0; j < 8; j++) acc[i][j] = 0ull;

#pragma unroll 4
    for (int kk = 0; kk < D / 2; kk++) {
        unsigned long long a[8], b[8];
#pragma unroll
        for (int i = 0; i < 8; i++) a[i] = sA[(ty * 8 + i) * 65 + kk];
#pragma unroll
        for (int j = 0; j < 8; j++) b[j] = sW[kk * 128 + tx + 16 * j];
#pragma unroll
        for (int i = 0; i < 8; i++)
#pragma unroll
            for (int j = 0; j < 8; j++) fma2(acc[i][j], a[i], b[j]);
    }

    float bc[8];
#pragma unroll
    for (int j = 0; j < 8; j++) bc[j] = b_node[nt * D + tx + 16 * j];

    __syncthreads();
#pragma unroll
    for (int i = 0; i < 8; i++) {
        int r = ty * 8 + i;
#pragma unroll
        for (int j = 0; j < 8; j++) {
            float2 f = unpack2(acc[i][j]);
            sOut[r * 132 + tx + 16 * j] = f.x + f.y + bc[j];
        }
    }
    __syncthreads();

    {
        int r = tid >> 1, half = tid & 1;
        int n = sNode[r];
        if (n >= 0) {
            const float* ap = g_agg + (size_t)n * D + half * 64;
            float* op = out + (size_t)n * D + half * 64;
            const float* sp = sOut + r * 132 + half * 64;
#pragma unroll
            for (int m = 0; m < 16; m++) {
                float4 v = *(const float4*)(sp + 4 * m);
                float4 a = *(const float4*)(ap + 4 * m);
                float4 o;
                o.x = fmaxf(v.x + a.x, 0.0f);
                o.y = fmaxf(v.y + a.y, 0.0f);
                o.z = fmaxf(v.z + a.z, 0.0f);
                o.w = fmaxf(v.w + a.w, 0.0f);
                *(float4*)(op + 4 * m) = o;
            }
        }
    }
}

/* ------------------------------ launch ------------------------------ */
extern "C" void kernel_launch(void* const* d_in, const int* in_sizes, int n_in,
                              void* d_out, int out_size) {
    const float* feats  = (const float*)d_in[0];
    const float* W_edge = (const float*)d_in[1];
    const float* b_edge = (const float*)d_in[2];
    const float* W_node = (const float*)d_in[3];
    const float* b_node = (const float*)d_in[4];
    const int* src    = (const int*)d_in[5];
    const int* dst    = (const int*)d_in[6];
    const int* ntypes = (const int*)d_in[7];
    const int* etypes = (const int*)d_in[8];
    float* out = (float*)d_out;
    (void)in_sizes; (void)n_in; (void)out_size;

    cudaFuncSetAttribute(k_edge, cudaFuncAttributeMaxDynamicSharedMemorySize, SMEM_BYTES);
    cudaFuncSetAttribute(k_node2, cudaFuncAttributeMaxDynamicSharedMemorySize, SMEM_BYTES);

    k_zero<<<1024, 256>>>();
    k_hist<<<640, 256>>>(dst, etypes, ntypes);
    k_scan<<<1, 1>>>();
    k_scatter<<<160, 256>>>(etypes, ntypes);
    k_edge<<<EG, 256, SMEM_BYTES>>>(feats, W_edge, b_edge, src, dst, etypes);
    k_node2<<<NG, 256, SMEM_BYTES>>>(feats, W_node, b_node, ntypes, out);
}

// round 3
// speedup vs baseline: 1.7925x; 1.7925x over previous
#include <cuda_runtime.h>
#include <cstdint>

#define N_NODES 50000
#define N_EDGES 640000
#define D 128
#define N_RELS 16
#define N_NT 8
#define TILE 128

#define EG (N_EDGES / TILE + N_RELS)            /* 5016 tiles max for edge gemm */
#define NG ((N_NODES + TILE - 1) / TILE + N_NT) /* 399 tiles max for node gemm */
#define E_PAD (EG * TILE)
#define N_PAD (NG * TILE)

#define SROW 132                      /* padded smem row stride (floats) */
#define GEMM_SMEM (2 * 128 * SROW * 4) /* sA + sB = 135168 B */
#define WT_SMEM (128 * 132 * 4)

/* ------------------------------ scratch ------------------------------ */
__device__ int   g_counts[N_NODES * N_RELS];
__device__ int   g_rel_cnt[N_RELS];
__device__ int   g_rel_cur[N_RELS];
__device__ int   g_nt_cnt[N_NT];
__device__ int   g_nt_cur[N_NT];
__device__ int   g_eperm[E_PAD];
__device__ int   g_nperm[N_PAD];
__device__ float g_agg[N_NODES * D];
__device__ int   g_ntiles[2];
__device__ float g_WT[N_RELS * D * D];  /* W_edge^T: [r][f][d], tf32-rounded */
__device__ float g_WnT[N_NT * D * D];   /* W_node^T */

/* ------------------------------ helpers ------------------------------ */
__device__ __forceinline__ uint32_t tf32r(float x) {
    uint32_t r;
    asm("cvt.rna.tf32.f32 %0, %1;" : "=r"(r) : "f"(x));
    return r;
}
__device__ __forceinline__ void mma8(float* c, const uint32_t* a, const uint32_t* b) {
    asm volatile(
        "mma.sync.aligned.m16n8k8.row.col.f32.tf32.tf32.f32 "
        "{%0,%1,%2,%3}, {%4,%5,%6,%7}, {%8,%9}, {%0,%1,%2,%3};"
        : "+f"(c[0]), "+f"(c[1]), "+f"(c[2]), "+f"(c[3])
        : "r"(a[0]), "r"(a[1]), "r"(a[2]), "r"(a[3]), "r"(b[0]), "r"(b[1]));
}
__device__ __forceinline__ void red2(float* p, float x, float y) {
    asm volatile("red.global.add.v2.f32 [%0], {%1,%2};" :: "l"(p), "f"(x), "f"(y) : "memory");
}

/* ------------------------------ setup kernels ------------------------------ */
__global__ void k_zero() {
    int i = blockIdx.x * blockDim.x + threadIdx.x;
    int stride = gridDim.x * blockDim.x;
    for (int j = i; j < N_NODES * D; j += stride) g_agg[j] = 0.0f;
    for (int j = i; j < N_NODES * N_RELS; j += stride) g_counts[j] = 0;
    for (int j = i; j < E_PAD; j += stride) g_eperm[j] = -1;
    for (int j = i; j < N_PAD; j += stride) g_nperm[j] = -1;
    if (i < N_RELS) g_rel_cnt[i] = 0;
    if (i < N_NT) g_nt_cnt[i] = 0;
}

__global__ void k_hist(const int* __restrict__ dst, const int* __restrict__ etypes,
                       const int* __restrict__ ntypes) {
    __shared__ int sh[N_RELS + N_NT];
    int tid = threadIdx.x;
    if (tid < N_RELS + N_NT) sh[tid] = 0;
    __syncthreads();
    int i = blockIdx.x * blockDim.x + tid;
    int stride = gridDim.x * blockDim.x;
    for (int e = i; e < N_EDGES; e += stride) {
        int t = etypes[e];
        atomicAdd(&sh[t], 1);
        atomicAdd(&g_counts[dst[e] * N_RELS + t], 1);
    }
    for (int n = i; n < N_NODES; n += stride) atomicAdd(&sh[N_RELS + ntypes[n]], 1);
    __syncthreads();
    if (tid < N_RELS) atomicAdd(&g_rel_cnt[tid], sh[tid]);
    else if (tid < N_RELS + N_NT) atomicAdd(&g_nt_cnt[tid - N_RELS], sh[tid]);
}

__global__ void k_scan() {
    int off = 0;
    for (int t = 0; t < N_RELS; t++) {
        g_rel_cur[t] = off;
        off += ((g_rel_cnt[t] + TILE - 1) / TILE) * TILE;
    }
    g_ntiles[0] = off / TILE;
    off = 0;
    for (int t = 0; t < N_NT; t++) {
        g_nt_cur[t] = off;
        off += ((g_nt_cnt[t] + TILE - 1) / TILE) * TILE;
    }
    g_ntiles[1] = off / TILE;
}

__global__ void k_scatter(const int* __restrict__ etypes, const int* __restrict__ ntypes) {
    __shared__ int s_cnt[N_RELS], s_base[N_RELS];
    const int CH = 2048;
    int tid = threadIdx.x;

    int nch = (N_EDGES + CH - 1) / CH;
    for (int ch = blockIdx.x; ch < nch; ch += gridDim.x) {
        int lo = ch * CH, hi = min(lo + CH, N_EDGES);
        if (tid < N_RELS) s_cnt[tid] = 0;
        __syncthreads();
        for (int e = lo + tid; e < hi; e += blockDim.x) atomicAdd(&s_cnt[etypes[e]], 1);
        __syncthreads();
        if (tid < N_RELS) {
            s_base[tid] = atomicAdd(&g_rel_cur[tid], s_cnt[tid]);
            s_cnt[tid] = 0;
        }
        __syncthreads();
        for (int e = lo + tid; e < hi; e += blockDim.x) {
            int t = etypes[e];
            g_eperm[s_base[t] + atomicAdd(&s_cnt[t], 1)] = e;
        }
        __syncthreads();
    }

    nch = (N_NODES + CH - 1) / CH;
    for (int ch = blockIdx.x; ch < nch; ch += gridDim.x) {
        int lo = ch * CH, hi = min(lo + CH, N_NODES);
        if (tid < N_NT) s_cnt[tid] = 0;
        __syncthreads();
        for (int n = lo + tid; n < hi; n += blockDim.x) atomicAdd(&s_cnt[ntypes[n]], 1);
        __syncthreads();
        if (tid < N_NT) {
            s_base[tid] = atomicAdd(&g_nt_cur[tid], s_cnt[tid]);
            s_cnt[tid] = 0;
        }
        __syncthreads();
        for (int n = lo + tid; n < hi; n += blockDim.x) {
            int t = ntypes[n];
            g_nperm[s_base[t] + atomicAdd(&s_cnt[t], 1)] = n;
        }
        __syncthreads();
    }
}

/* Transpose + tf32-round weights: g_WT[m][f*128+d] = rna_tf32(W[m][d*128+f]) */
__global__ void k_wt(const float* __restrict__ We, const float* __restrict__ Wn) {
    extern __shared__ float sT[]; /* [128][132] */
    int m = blockIdx.x;
    const float* Wsrc = (m < N_RELS) ? We + (size_t)m * D * D : Wn + (size_t)(m - N_RELS) * D * D;
    float* Wdst = (m < N_RELS) ? g_WT + (size_t)m * D * D : g_WnT + (size_t)(m - N_RELS) * D * D;
    int tid = threadIdx.x;
#pragma unroll
    for (int i = 0; i < 16; i++) {
        int lin = tid + 256 * i;    /* float4 id */
        int d = lin >> 5, fq = lin & 31;
        float4 v = *(const float4*)(Wsrc + d * D + fq * 4);
        sT[d * 132 + fq * 4 + 0] = __uint_as_float(tf32r(v.x));
        sT[d * 132 + fq * 4 + 1] = __uint_as_float(tf32r(v.y));
        sT[d * 132 + fq * 4 + 2] = __uint_as_float(tf32r(v.z));
        sT[d * 132 + fq * 4 + 3] = __uint_as_float(tf32r(v.w));
    }
    __syncthreads();
#pragma unroll
    for (int i = 0; i < 16; i++) {
        int lin = tid + 256 * i;
        int f = lin >> 5, dq = lin & 31;
        float4 v;
        v.x = sT[(dq * 4 + 0) * 132 + f];
        v.y = sT[(dq * 4 + 1) * 132 + f];
        v.z = sT[(dq * 4 + 2) * 132 + f];
        v.w = sT[(dq * 4 + 3) * 132 + f];
        *(float4*)(Wdst + f * D + dq * 4) = v;
    }
}

/* ------------------------------ mma.sync edge GEMM ------------------------------ */
/* Block = 128 edges of one relation. 256 thr = 8 warps as 2(m)x4(n); each warp
 * owns 64 rows x 32 cols = 4x4 m16n8 accumulator tiles, K=128 in 16 k8 steps. */
__global__ __launch_bounds__(256, 1) void k_edge_mma(
    const float* __restrict__ feats, const float* __restrict__ b_edge,
    const int* __restrict__ src, const int* __restrict__ dst,
    const int* __restrict__ etypes) {
    if ((int)blockIdx.x >= g_ntiles[0]) return;

    extern __shared__ float smf[];
    float* sA = smf;                  /* [128][SROW] */
    float* sB = smf + 128 * SROW;     /* [128][SROW] : sB[n][k] = W^T[n][k] */
    const uint32_t* sAu = (const uint32_t*)sA;
    const uint32_t* sBu = (const uint32_t*)sB;

    __shared__ int sDst[TILE], sSrc[TILE];
    __shared__ float sInv[TILE], sBias[TILE];
    __shared__ int sRel;

    const int tid = threadIdx.x, wid = tid >> 5, lane = tid & 31;
    const int base = blockIdx.x * TILE;

    if (tid < TILE) {
        int e = g_eperm[base + tid];
        int d_ = -1, s_ = 0;
        float inv = 0.0f;
        if (e >= 0) {
            d_ = dst[e];
            s_ = src[e];
            int t = etypes[e];
            inv = 1.0f / (float)g_counts[d_ * N_RELS + t];
            if (tid == 0) sRel = t;
        }
        sDst[tid] = d_;
        sSrc[tid] = s_;
        sInv[tid] = inv;
    }
    __syncthreads();
    const int rel = sRel;
    if (tid < TILE) sBias[tid] = b_edge[rel * D + tid];

    /* gather A rows (tf32-rounded) */
    {
        int r = tid >> 1, half = tid & 1;
        const float4* fp = (const float4*)(feats + (size_t)sSrc[r] * D) + half * 16;
        float* ap = sA + r * SROW + half * 64;
#pragma unroll
        for (int i = 0; i < 16; i++) {
            float4 v = fp[i];
            float4 o;
            o.x = __uint_as_float(tf32r(v.x));
            o.y = __uint_as_float(tf32r(v.y));
            o.z = __uint_as_float(tf32r(v.z));
            o.w = __uint_as_float(tf32r(v.w));
            *(float4*)(ap + i * 4) = o;
        }
    }
    /* copy B = g_WT[rel] (pre-rounded) */
    {
        const float* Wr = g_WT + (size_t)rel * D * D;
#pragma unroll
        for (int i = 0; i < 16; i++) {
            int lin = tid + 256 * i;
            int f = lin >> 5, kq = lin & 31;
            *(float4*)(sB + f * SROW + kq * 4) = *(const float4*)(Wr + f * D + kq * 4);
        }
    }
    __syncthreads();

    const int wm = wid & 1, wn = wid >> 1;
    const int r_base = wm * 64, c_base = wn * 32;
    const int lq = lane >> 2, lr = lane & 3;

    float acc[4][4][4];
#pragma unroll
    for (int mt = 0; mt < 4; mt++)
#pragma unroll
        for (int nt = 0; nt < 4; nt++)
#pragma unroll
            for (int j = 0; j < 4; j++) acc[mt][nt][j] = 0.0f;

#pragma unroll 4
    for (int k0 = 0; k0 < 16; k0++) {
        const int kk = k0 * 8 + lr;
        uint32_t a[4][4], b[4][2];
#pragma unroll
        for (int mt = 0; mt < 4; mt++) {
            int row = r_base + mt * 16 + lq;
            a[mt][0] = sAu[row * SROW + kk];
            a[mt][1] = sAu[(row + 8) * SROW + kk];
            a[mt][2] = sAu[row * SROW + kk + 4];
            a[mt][3] = sAu[(row + 8) * SROW + kk + 4];
        }
#pragma unroll
        for (int nt = 0; nt < 4; nt++) {
            int n = c_base + nt * 8 + lq;
            b[nt][0] = sBu[n * SROW + kk];
            b[nt][1] = sBu[n * SROW + kk + 4];
        }
#pragma unroll
        for (int mt = 0; mt < 4; mt++)
#pragma unroll
            for (int nt = 0; nt < 4; nt++) mma8(acc[mt][nt], a[mt], b[nt]);
    }

    /* epilogue: (acc + bias) * inv, red.v2 into g_agg */
#pragma unroll
    for (int mt = 0; mt < 4; mt++) {
        int row0 = r_base + mt * 16 + lq;
#pragma unroll
        for (int h = 0; h < 2; h++) {
            int rr = row0 + h * 8;
            int dn = sDst[rr];
            if (dn < 0) continue;
            float inv = sInv[rr];
            float* gb = g_agg + (size_t)dn * D;
#pragma unroll
            for (int nt = 0; nt < 4; nt++) {
                int col = c_base + nt * 8 + lr * 2;
                float x = (acc[mt][nt][h * 2 + 0] + sBias[col]) * inv;
                float y = (acc[mt][nt][h * 2 + 1] + sBias[col + 1]) * inv;
                red2(gb + col, x, y);
            }
        }
    }
}

/* ------------------------------ mma.sync node GEMM + residual + relu ------------------------------ */
__global__ __launch_bounds__(256, 1) void k_node_mma(
    const float* __restrict__ feats, const float* __restrict__ b_node,
    const int* __restrict__ ntypes, float* __restrict__ out) {
    if ((int)blockIdx.x >= g_ntiles[1]) return;

    extern __shared__ float smf[];
    float* sA = smf;
    float* sB = smf + 128 * SROW;
    const uint32_t* sAu = (const uint32_t*)sA;
    const uint32_t* sBu = (const uint32_t*)sB;

    __shared__ int sNode[TILE];
    __shared__ float sBias[TILE];
    __shared__ int sNt;

    const int tid = threadIdx.x, wid = tid >> 5, lane = tid & 31;
    const int base = blockIdx.x * TILE;

    if (tid < TILE) {
        int n = g_nperm[base + tid];
        sNode[tid] = n;
        if (tid == 0) sNt = ntypes[n]; /* row 0 of a live tile is always valid */
    }
    __syncthreads();
    const int nt_ = sNt;
    if (tid < TILE) sBias[tid] = b_node[nt_ * D + tid];

    {
        int r = tid >> 1, half = tid & 1;
        int n = sNode[r];
        const float4* fp = (const float4*)(feats + (size_t)(n >= 0 ? n : 0) * D) + half * 16;
        float* ap = sA + r * SROW + half * 64;
#pragma unroll
        for (int i = 0; i < 16; i++) {
            float4 v = fp[i];
            float4 o;
            o.x = __uint_as_float(tf32r(v.x));
            o.y = __uint_as_float(tf32r(v.y));
            o.z = __uint_as_float(tf32r(v.z));
            o.w = __uint_as_float(tf32r(v.w));
            *(float4*)(ap + i * 4) = o;
        }
    }
    {
        const float* Wr = g_WnT + (size_t)nt_ * D * D;
#pragma unroll
        for (int i = 0; i < 16; i++) {
            int lin = tid + 256 * i;
            int f = lin >> 5, kq = lin & 31;
            *(float4*)(sB + f * SROW + kq * 4) = *(const float4*)(Wr + f * D + kq * 4);
        }
    }
    __syncthreads();

    const int wm = wid & 1, wn = wid >> 1;
    const int r_base = wm * 64, c_base = wn * 32;
    const int lq = lane >> 2, lr = lane & 3;

    float acc[4][4][4];
#pragma unroll
    for (int mt = 0; mt < 4; mt++)
#pragma unroll
        for (int ntl = 0; ntl < 4; ntl++)
#pragma unroll
            for (int j = 0; j < 4; j++) acc[mt][ntl][j] = 0.0f;

#pragma unroll 4
    for (int k0 = 0; k0 < 16; k0++) {
        const int kk = k0 * 8 + lr;
        uint32_t a[4][4], b[4][2];
#pragma unroll
        for (int mt = 0; mt < 4; mt++) {
            int row = r_base + mt * 16 + lq;
            a[mt][0] = sAu[row * SROW + kk];
            a[mt][1] = sAu[(row + 8) * SROW + kk];
            a[mt][2] = sAu[row * SROW + kk + 4];
            a[mt][3] = sAu[(row + 8) * SROW + kk + 4];
        }
#pragma unroll
        for (int ntl = 0; ntl < 4; ntl++) {
            int n = c_base + ntl * 8 + lq;
            b[ntl][0] = sBu[n * SROW + kk];
            b[ntl][1] = sBu[n * SROW + kk + 4];
        }
#pragma unroll
        for (int mt = 0; mt < 4; mt++)
#pragma unroll
            for (int ntl = 0; ntl < 4; ntl++) mma8(acc[mt][ntl], a[mt], b[ntl]);
    }

    /* epilogue: relu(acc + bias + agg) -> out */
#pragma unroll
    for (int mt = 0; mt < 4; mt++) {
        int row0 = r_base + mt * 16 + lq;
#pragma unroll
        for (int h = 0; h < 2; h++) {
            int rr = row0 + h * 8;
            int n = sNode[rr];
            if (n < 0) continue;
            const float* ab = g_agg + (size_t)n * D;
            float* ob = out + (size_t)n * D;
#pragma unroll
            for (int ntl = 0; ntl < 4; ntl++) {
                int col = c_base + ntl * 8 + lr * 2;
                float2 ag = *(const float2*)(ab + col);
                float2 o;
                o.x = fmaxf(acc[mt][ntl][h * 2 + 0] + sBias[col] + ag.x, 0.0f);
                o.y = fmaxf(acc[mt][ntl][h * 2 + 1] + sBias[col + 1] + ag.y, 0.0f);
                *(float2*)(ob + col) = o;
            }
        }
    }
}

/* ------------------------------ launch ------------------------------ */
extern "C" void kernel_launch(void* const* d_in, const int* in_sizes, int n_in,
                              void* d_out, int out_size) {
    const float* feats  = (const float*)d_in[0];
    const float* W_edge = (const float*)d_in[1];
    const float* b_edge = (const float*)d_in[2];
    const float* W_node = (const float*)d_in[3];
    const float* b_node = (const float*)d_in[4];
    const int* src    = (const int*)d_in[5];
    const int* dst    = (const int*)d_in[6];
    const int* ntypes = (const int*)d_in[7];
    const int* etypes = (const int*)d_in[8];
    float* out = (float*)d_out;
    (void)in_sizes; (void)n_in; (void)out_size;

    cudaFuncSetAttribute(k_edge_mma, cudaFuncAttributeMaxDynamicSharedMemorySize, GEMM_SMEM);
    cudaFuncSetAttribute(k_node_mma, cudaFuncAttributeMaxDynamicSharedMemorySize, GEMM_SMEM);
    cudaFuncSetAttribute(k_wt, cudaFuncAttributeMaxDynamicSharedMemorySize, WT_SMEM);

    k_zero<<<1024, 256>>>();
    k_hist<<<640, 256>>>(dst, etypes, ntypes);
    k_wt<<<N_RELS + N_NT, 256, WT_SMEM>>>(W_edge, W_node);
    k_scan<<<1, 1>>>();
    k_scatter<<<320, 256>>>(etypes, ntypes);
    k_edge_mma<<<EG, 256, GEMM_SMEM>>>(feats, b_edge, src, dst, etypes);
    k_node_mma<<<NG, 256, GEMM_SMEM>>>(feats, b_node, ntypes, out);
}